// round 8
// baseline (speedup 1.0000x reference)
#include <cuda_runtime.h>

typedef unsigned long long ull;

// out = (w1+w2)*s + (w3-w2)*G3(s) + (w4-w3)*G5(s) - w4*G7(s)
// Smem-free warp-streaming with distance-7 software pipeline:
//   - float4 buf[7] rolling prefetch ring for main rows (MLP=7)
//   - lane-distributed edge-halo prefetch (lane j holds row j's halo), shfl broadcast
//   - horizontal taps via lane shuffles (FFMA-imm), vertical via transposed-FIR f32x2 ring

#define IMG 512
#define CHUNK 64
#define STEPS (CHUNK + 6)    // 70
#define NTH 128
#define WPB (NTH / 32)

#define K3_0 0.5220116f
#define K3_1 0.2389942f
#define K5_0 0.3695467f
#define K5_1 0.2444604f
#define K5_2 0.0707663f
#define K7_0 0.2880262f
#define K7_1 0.2231734f
#define K7_2 0.1038183f
#define K7_3 0.0289952f

__device__ __forceinline__ ull pk2(float lo, float hi) {
    ull r; asm("mov.b64 %0, {%1, %2};" : "=l"(r) : "f"(lo), "f"(hi)); return r;
}
__device__ __forceinline__ ull mul2(ull a, ull b) {
    ull r; asm("mul.rn.f32x2 %0, %1, %2;" : "=l"(r) : "l"(a), "l"(b)); return r;
}
__device__ __forceinline__ ull fma2(ull a, ull b, ull c) {
    ull r; asm("fma.rn.f32x2 %0, %1, %2, %3;" : "=l"(r) : "l"(a), "l"(b), "l"(c)); return r;
}

__global__ void __launch_bounds__(NTH, 5)
mgdf_kernel(const float* __restrict__ s,
            const float* __restrict__ w1p, const float* __restrict__ w2p,
            const float* __restrict__ w3p, const float* __restrict__ w4p,
            float* __restrict__ out)
{
    const int lane = threadIdx.x & 31;
    const int wid  = threadIdx.x >> 5;
    const int g = blockIdx.x * WPB + wid;     // global warp id
    const int img   = g >> 5;                 // 32 warps per image
    const int strip = g & 3;                  // 4 col-strips of 128
    const int chunk = (g >> 2) & 7;           // 8 row-chunks of 64

    const size_t ibase = (size_t)img * (IMG * IMG);
    const int col = strip * 128 + lane * 4;
    const int gy0 = chunk * CHUNK - 3;

    const float* rc = s + ibase + (size_t)gy0 * IMG + col;  // deref only when row valid
    float* oc = out + ibase + (size_t)(chunk * CHUNK) * IMG + col;
    const float* eL = s + ibase + (strip * 128 - 4);        // + gy*IMG per row
    const float* eR = s + ibase + (strip * 128 + 128);
    const bool hasL = (strip > 0), hasR = (strip < 3);

    // Runtime weights folded into vertical coefficients
    const float W1 = *w1p, W2 = *w2p, W3 = *w3p, W4 = *w4p;
    const float cA = W1 + W2, cB = W3 - W2, cC = W4 - W3, cD = -W4;
    const ull cAp = pk2(cA, cA);
    const ull a30 = pk2(cB * K3_0, cB * K3_0);
    const ull a31 = pk2(cB * K3_1, cB * K3_1);
    const ull a50 = pk2(cC * K5_0, cC * K5_0);
    const ull a51 = pk2(cC * K5_1, cC * K5_1);
    const ull a52 = pk2(cC * K5_2, cC * K5_2);
    const ull a70 = pk2(cD * K7_0, cD * K7_0);
    const ull a71 = pk2(cD * K7_1, cD * K7_1);
    const ull a72 = pk2(cD * K7_2, cD * K7_2);
    const ull a73 = pk2(cD * K7_3, cD * K7_3);

    const float4 z4 = make_float4(0.f, 0.f, 0.f, 0.f);

    // ---- prologue: prefetch rows gy0..gy0+6 (MLP=7) + lane-distributed halos ----
    float4 buf[7];
    #pragma unroll
    for (int j = 0; j < 7; j++) {
        int gy = gy0 + j;
        buf[j] = z4;
        if ((unsigned)gy < (unsigned)IMG)
            buf[j] = *reinterpret_cast<const float4*>(rc + (size_t)j * IMG);
    }
    float4 elb = z4, erb = z4;   // lane j holds row (group base + j)'s halos
    {
        int gy = gy0 + lane;
        if (lane < 7 && (unsigned)gy < (unsigned)IMG) {
            if (hasL) elb = *reinterpret_cast<const float4*>(eL + (size_t)gy * IMG);
            if (hasR) erb = *reinterpret_cast<const float4*>(eR + (size_t)gy * IMG);
        }
    }

    ull acc[7][2];
    int gy = gy0;

// One pipeline step: consume buf[j] (row k), optionally prefetch row k+7 into slot j.
#define STEP(j, kk, PF)                                                          \
    {                                                                            \
        const int k = (kk);                                                      \
        float4 B = buf[j];                                                       \
        /* broadcast this row's halos from lane j BEFORE lane j reloads */       \
        float el1 = __shfl_sync(0xFFFFFFFFu, elb.y, (j));                        \
        float el2 = __shfl_sync(0xFFFFFFFFu, elb.z, (j));                        \
        float el3 = __shfl_sync(0xFFFFFFFFu, elb.w, (j));                        \
        float er1 = __shfl_sync(0xFFFFFFFFu, erb.x, (j));                        \
        float er2 = __shfl_sync(0xFFFFFFFFu, erb.y, (j));                        \
        float er3 = __shfl_sync(0xFFFFFFFFu, erb.z, (j));                        \
        if (PF) {                                                                \
            int gyp = gy + 7;                                                    \
            float4 nb = z4;                                                      \
            if ((unsigned)gyp < (unsigned)IMG)                                   \
                nb = *reinterpret_cast<const float4*>(rc + 7 * IMG);             \
            buf[j] = nb;                                                         \
            if (lane == (j)) {                                                   \
                elb = z4; erb = z4;                                              \
                if ((unsigned)gyp < (unsigned)IMG) {                             \
                    if (hasL) elb = *reinterpret_cast<const float4*>(eL + (size_t)gyp * IMG); \
                    if (hasR) erb = *reinterpret_cast<const float4*>(eR + (size_t)gyp * IMG); \
                }                                                                \
            }                                                                    \
        }                                                                        \
        float x1 = __shfl_up_sync(0xFFFFFFFFu, B.y, 1);                          \
        float x2 = __shfl_up_sync(0xFFFFFFFFu, B.z, 1);                          \
        float x3 = __shfl_up_sync(0xFFFFFFFFu, B.w, 1);                          \
        float x8 = __shfl_down_sync(0xFFFFFFFFu, B.x, 1);                        \
        float x9 = __shfl_down_sync(0xFFFFFFFFu, B.y, 1);                        \
        float x10 = __shfl_down_sync(0xFFFFFFFFu, B.z, 1);                       \
        if (lane == 0)  { x1 = el1; x2 = el2; x3 = el3; }                        \
        if (lane == 31) { x8 = er1; x9 = er2; x10 = er3; }                       \
        const float x4 = B.x, x5 = B.y, x6 = B.z, x7 = B.w;                      \
        float h3v[4], h5v[4], h7v[4];                                            \
        {                                                                        \
            float p1, p2, p3;                                                    \
            p1 = x3 + x5;  p2 = x2 + x6;  p3 = x1 + x7;                          \
            h3v[0] = K3_0 * x4 + K3_1 * p1;                                      \
            h5v[0] = K5_0 * x4 + K5_1 * p1 + K5_2 * p2;                          \
            h7v[0] = K7_0 * x4 + K7_1 * p1 + K7_2 * p2 + K7_3 * p3;              \
            p1 = x4 + x6;  p2 = x3 + x7;  p3 = x2 + x8;                          \
            h3v[1] = K3_0 * x5 + K3_1 * p1;                                      \
            h5v[1] = K5_0 * x5 + K5_1 * p1 + K5_2 * p2;                          \
            h7v[1] = K7_0 * x5 + K7_1 * p1 + K7_2 * p2 + K7_3 * p3;              \
            p1 = x5 + x7;  p2 = x4 + x8;  p3 = x3 + x9;                          \
            h3v[2] = K3_0 * x6 + K3_1 * p1;                                      \
            h5v[2] = K5_0 * x6 + K5_1 * p1 + K5_2 * p2;                          \
            h7v[2] = K7_0 * x6 + K7_1 * p1 + K7_2 * p2 + K7_3 * p3;              \
            p1 = x6 + x8;  p2 = x5 + x9;  p3 = x4 + x10;                         \
            h3v[3] = K3_0 * x7 + K3_1 * p1;                                      \
            h5v[3] = K5_0 * x7 + K5_1 * p1 + K5_2 * p2;                          \
            h7v[3] = K7_0 * x7 + K7_1 * p1 + K7_2 * p2 + K7_3 * p3;              \
        }                                                                        \
        ull t3a = pk2(h3v[0], h3v[1]), t3b = pk2(h3v[2], h3v[3]);                \
        ull t5a = pk2(h5v[0], h5v[1]), t5b = pk2(h5v[2], h5v[3]);                \
        ull t7a = pk2(h7v[0], h7v[1]), t7b = pk2(h7v[2], h7v[3]);                \
        ull rwa = pk2(x4, x5),          rwb = pk2(x6, x7);                       \
        acc[(j)][0] = mul2(a73, t7a);                                            \
        acc[(j)][1] = mul2(a73, t7b);                                            \
        {   const int sl = ((j) + 6) % 7;                                        \
            ull u = acc[sl][0], v = acc[sl][1];                                  \
            u = fma2(a72, t7a, u);  v = fma2(a72, t7b, v);                       \
            u = fma2(a52, t5a, u);  v = fma2(a52, t5b, v);                       \
            acc[sl][0] = u; acc[sl][1] = v; }                                    \
        {   const int sl = ((j) + 5) % 7;                                        \
            ull u = acc[sl][0], v = acc[sl][1];                                  \
            u = fma2(a71, t7a, u);  v = fma2(a71, t7b, v);                       \
            u = fma2(a51, t5a, u);  v = fma2(a51, t5b, v);                       \
            u = fma2(a31, t3a, u);  v = fma2(a31, t3b, v);                       \
            acc[sl][0] = u; acc[sl][1] = v; }                                    \
        {   const int sl = ((j) + 4) % 7;                                        \
            ull u = acc[sl][0], v = acc[sl][1];                                  \
            u = fma2(a70, t7a, u);  v = fma2(a70, t7b, v);                       \
            u = fma2(a50, t5a, u);  v = fma2(a50, t5b, v);                       \
            u = fma2(a30, t3a, u);  v = fma2(a30, t3b, v);                       \
            u = fma2(cAp, rwa, u);  v = fma2(cAp, rwb, v);                       \
            acc[sl][0] = u; acc[sl][1] = v; }                                    \
        {   const int sl = ((j) + 3) % 7;                                        \
            ull u = acc[sl][0], v = acc[sl][1];                                  \
            u = fma2(a71, t7a, u);  v = fma2(a71, t7b, v);                       \
            u = fma2(a51, t5a, u);  v = fma2(a51, t5b, v);                       \
            u = fma2(a31, t3a, u);  v = fma2(a31, t3b, v);                       \
            acc[sl][0] = u; acc[sl][1] = v; }                                    \
        {   const int sl = ((j) + 2) % 7;                                        \
            ull u = acc[sl][0], v = acc[sl][1];                                  \
            u = fma2(a72, t7a, u);  v = fma2(a72, t7b, v);                       \
            u = fma2(a52, t5a, u);  v = fma2(a52, t5b, v);                       \
            acc[sl][0] = u; acc[sl][1] = v; }                                    \
        if (k >= 6) {                                                            \
            const int sl = ((j) + 1) % 7;                                        \
            ulonglong2 o;                                                        \
            o.x = fma2(a73, t7a, acc[sl][0]);                                    \
            o.y = fma2(a73, t7b, acc[sl][1]);                                    \
            *reinterpret_cast<ulonglong2*>(oc) = o;                              \
            oc += IMG;                                                           \
        }                                                                        \
        gy++;                                                                    \
        rc += IMG;                                                               \
    }

    // groups 0..8: steady-state with prefetch of row k+7
    for (int i = 0; i < 9; i++) {
        const int kb = i * 7;
        STEP(0, kb + 0, true)
        STEP(1, kb + 1, true)
        STEP(2, kb + 2, true)
        STEP(3, kb + 3, true)
        STEP(4, kb + 4, true)
        STEP(5, kb + 5, true)
        STEP(6, kb + 6, true)
    }
    // final group: rows 63..69, no prefetch
    STEP(0, 63, false)
    STEP(1, 64, false)
    STEP(2, 65, false)
    STEP(3, 66, false)
    STEP(4, 67, false)
    STEP(5, 68, false)
    STEP(6, 69, false)

#undef STEP
}

extern "C" void kernel_launch(void* const* d_in, const int* in_sizes, int n_in,
                              void* d_out, int out_size)
{
    const float* s  = (const float*)d_in[0];
    const float* w1 = (const float*)d_in[1];
    const float* w2 = (const float*)d_in[2];
    const float* w3 = (const float*)d_in[3];
    const float* w4 = (const float*)d_in[4];
    float* out = (float*)d_out;

    const int n_img = in_sizes[0] / (IMG * IMG);        // 192
    const int n_warps = n_img * 32;                     // 4 strips x 8 chunks per image
    dim3 grid(n_warps / WPB, 1, 1);                     // 1536 blocks
    mgdf_kernel<<<grid, NTH>>>(s, w1, w2, w3, w4, out);
}

// round 9
// speedup vs baseline: 2.1141x; 2.1141x over previous
#include <cuda_runtime.h>
#include <cuda.h>

typedef unsigned long long ull;

// out = (w1+w2)*s + (w3-w2)*G3(s) + (w4-w3)*G5(s) - w4*G7(s)
// R4 structure (tile 128x64, 2 col/thread, FFMA-imm horizontal, transposed-FIR
// f32x2 vertical ring, 4 CTAs/SM) with the tile load moved to TMA (UTMALDG):
// zero LSU wavefronts + zero addressing ALU for the load, OOB zero-fill = conv padding.

#define IMG 512
#define TX 128
#define TY 64
#define NTH 256
#define SW 136            // TX + 8 (left halo 4, right halo 4)
#define SH 70             // TY + 6
#define NF4 (SW / 4)
#define STEPS 22
#define TILE_BYTES (SH * SW * 4)   // 38080

#define K3_0 0.5220116f
#define K3_1 0.2389942f
#define K5_0 0.3695467f
#define K5_1 0.2444604f
#define K5_2 0.0707663f
#define K7_0 0.2880262f
#define K7_1 0.2231734f
#define K7_2 0.1038183f
#define K7_3 0.0289952f

__device__ __forceinline__ ull pk2(float lo, float hi) {
    ull r; asm("mov.b64 %0, {%1, %2};" : "=l"(r) : "f"(lo), "f"(hi)); return r;
}
__device__ __forceinline__ ull mul2(ull a, ull b) {
    ull r; asm("mul.rn.f32x2 %0, %1, %2;" : "=l"(r) : "l"(a), "l"(b)); return r;
}
__device__ __forceinline__ ull fma2(ull a, ull b, ull c) {
    ull r; asm("fma.rn.f32x2 %0, %1, %2, %3;" : "=l"(r) : "l"(a), "l"(b), "l"(c)); return r;
}
__device__ __forceinline__ unsigned smem_u32(const void* p) {
    unsigned r;
    asm("{ .reg .u64 t; cvta.to.shared.u64 t, %1; cvt.u32.u64 %0, t; }" : "=r"(r) : "l"(p));
    return r;
}

// ---- shared compute body (identical to R4) ----
__device__ __forceinline__ void compute_tile(
    float (&tile)[SH][SW],
    const float* __restrict__ w1p, const float* __restrict__ w2p,
    const float* __restrict__ w3p, const float* __restrict__ w4p,
    float* __restrict__ op, int tileX, int tileY)
{
    const int tid = threadIdx.x;
    const float W1 = *w1p, W2 = *w2p, W3 = *w3p, W4 = *w4p;
    const float cA = W1 + W2, cB = W3 - W2, cC = W4 - W3, cD = -W4;
    const ull cAp = pk2(cA, cA);
    const ull a30 = pk2(cB * K3_0, cB * K3_0);
    const ull a31 = pk2(cB * K3_1, cB * K3_1);
    const ull a50 = pk2(cC * K5_0, cC * K5_0);
    const ull a51 = pk2(cC * K5_1, cC * K5_1);
    const ull a52 = pk2(cC * K5_2, cC * K5_2);
    const ull a70 = pk2(cD * K7_0, cD * K7_0);
    const ull a71 = pk2(cD * K7_1, cD * K7_1);
    const ull a72 = pk2(cD * K7_2, cD * K7_2);
    const ull a73 = pk2(cD * K7_3, cD * K7_3);

    const int xg = tid & 63;
    const int rg = tid >> 6;
    const int cs = 2 * xg + 4;
    const int rowBase = rg * 16;
    float* orow = op + (size_t)(tileY + rowBase) * IMG + tileX + 2 * xg;

    ull acc[7];

    #pragma unroll
    for (int k = 0; k < STEPS; k++) {
        const int sr = rowBase + k;

        float  x1 = tile[sr][cs - 3];
        float2 P1 = *reinterpret_cast<const float2*>(&tile[sr][cs - 2]);
        float2 P2 = *reinterpret_cast<const float2*>(&tile[sr][cs]);
        float2 P3 = *reinterpret_cast<const float2*>(&tile[sr][cs + 2]);
        float  x8 = tile[sr][cs + 4];

        float a_p1 = P1.y + P2.y;
        float a_p2 = P1.x + P3.x;
        float a_p3 = x1 + P3.y;
        float h3a = K3_0 * P2.x + K3_1 * a_p1;
        float h5a = K5_0 * P2.x + K5_1 * a_p1 + K5_2 * a_p2;
        float h7a = K7_0 * P2.x + K7_1 * a_p1 + K7_2 * a_p2 + K7_3 * a_p3;

        float b_p1 = P2.x + P3.x;
        float b_p2 = P1.y + P3.y;
        float b_p3 = P1.x + x8;
        float h3b = K3_0 * P2.y + K3_1 * b_p1;
        float h5b = K5_0 * P2.y + K5_1 * b_p1 + K5_2 * b_p2;
        float h7b = K7_0 * P2.y + K7_1 * b_p1 + K7_2 * b_p2 + K7_3 * b_p3;

        ull t3 = pk2(h3a, h3b);
        ull t5 = pk2(h5a, h5b);
        ull t7 = pk2(h7a, h7b);
        ull rw = pk2(P2.x, P2.y);

        // transposed-FIR ring (slots compile-time under full unroll)
        if (k <= 15) {
            acc[k % 7] = mul2(a73, t7);
        }
        if (k >= 1 && k <= 16) {
            ull a = acc[(k - 1) % 7];
            a = fma2(a72, t7, a);
            a = fma2(a52, t5, a);
            acc[(k - 1) % 7] = a;
        }
        if (k >= 2 && k <= 17) {
            ull a = acc[(k - 2) % 7];
            a = fma2(a71, t7, a);
            a = fma2(a51, t5, a);
            a = fma2(a31, t3, a);
            acc[(k - 2) % 7] = a;
        }
        if (k >= 3 && k <= 18) {
            ull a = acc[(k - 3) % 7];
            a = fma2(a70, t7, a);
            a = fma2(a50, t5, a);
            a = fma2(a30, t3, a);
            a = fma2(cAp, rw, a);
            acc[(k - 3) % 7] = a;
        }
        if (k >= 4 && k <= 19) {
            ull a = acc[(k - 4) % 7];
            a = fma2(a71, t7, a);
            a = fma2(a51, t5, a);
            a = fma2(a31, t3, a);
            acc[(k - 4) % 7] = a;
        }
        if (k >= 5 && k <= 20) {
            ull a = acc[(k - 5) % 7];
            a = fma2(a72, t7, a);
            a = fma2(a52, t5, a);
            acc[(k - 5) % 7] = a;
        }
        if (k >= 6) {
            ull r = fma2(a73, t7, acc[(k - 6) % 7]);
            *reinterpret_cast<ull*>(orow + (size_t)(k - 6) * IMG) = r;
        }
    }
}

// ---- TMA kernel: tile filled by one bulk 3D tensor copy ----
__global__ void __launch_bounds__(NTH, 4)
mgdf_tma_kernel(const __grid_constant__ CUtensorMap tmap,
                const float* __restrict__ w1p, const float* __restrict__ w2p,
                const float* __restrict__ w3p, const float* __restrict__ w4p,
                float* __restrict__ out)
{
    __shared__ __align__(128) float tile[SH][SW];
    __shared__ __align__(8) ull mbar;

    const int tid = threadIdx.x;
    const int tileX = blockIdx.x * TX;
    const int tileY = blockIdx.y * TY;
    const int img = blockIdx.z;
    float* op = out + (size_t)img * (IMG * IMG);

    const unsigned mb = smem_u32(&mbar);
    if (tid == 0) {
        asm volatile("mbarrier.init.shared.b64 [%0], 1;" :: "r"(mb) : "memory");
    }
    __syncthreads();
    if (tid == 0) {
        asm volatile("mbarrier.arrive.expect_tx.shared.b64 _, [%0], %1;"
                     :: "r"(mb), "r"((unsigned)TILE_BYTES) : "memory");
        asm volatile(
            "cp.async.bulk.tensor.3d.shared::cta.global.tile.mbarrier::complete_tx::bytes "
            "[%0], [%1, {%2, %3, %4}], [%5];"
            :: "r"(smem_u32(&tile[0][0])), "l"(&tmap),
               "r"(tileX - 4), "r"(tileY - 3), "r"(img), "r"(mb)
            : "memory");
    }
    // wait (acquire) for TMA completion, phase 0
    {
        unsigned done;
        asm volatile(
            "{\n\t.reg .pred p;\n\t"
            "mbarrier.try_wait.parity.acquire.cta.shared::cta.b64 p, [%1], 0;\n\t"
            "selp.b32 %0, 1, 0, p;\n\t}"
            : "=r"(done) : "r"(mb) : "memory");
        if (!done) {
            asm volatile(
                "{\n\t.reg .pred P1;\n\t"
                "W%=:\n\t"
                "mbarrier.try_wait.parity.acquire.cta.shared::cta.b64 P1, [%0], 0, 0x989680;\n\t"
                "@P1 bra.uni D%=;\n\t"
                "bra.uni W%=;\n\t"
                "D%=:\n\t}"
                :: "r"(mb) : "memory");
        }
    }

    compute_tile(tile, w1p, w2p, w3p, w4p, op, tileX, tileY);
}

// ---- fallback kernel: R4-style LDG tile load (used if TMA encode unavailable) ----
__global__ void __launch_bounds__(NTH, 4)
mgdf_ldg_kernel(const float* __restrict__ s,
                const float* __restrict__ w1p, const float* __restrict__ w2p,
                const float* __restrict__ w3p, const float* __restrict__ w4p,
                float* __restrict__ out)
{
    __shared__ __align__(16) float tile[SH][SW];

    const int img = blockIdx.z;
    const size_t base = (size_t)img * (IMG * IMG);
    const float* sp = s + base;
    float* op = out + base;
    const int tileX = blockIdx.x * TX;
    const int tileY = blockIdx.y * TY;
    const int tid = threadIdx.x;

    #pragma unroll
    for (int idx = tid; idx < SH * NF4; idx += NTH) {
        int r = idx / NF4;
        int c4 = idx - r * NF4;
        int gy = tileY - 3 + r;
        int gx = tileX - 4 + c4 * 4;
        float4 v = make_float4(0.f, 0.f, 0.f, 0.f);
        if ((unsigned)gy < (unsigned)IMG && (unsigned)gx < (unsigned)IMG)
            v = *reinterpret_cast<const float4*>(sp + gy * IMG + gx);
        *reinterpret_cast<float4*>(&tile[r][c4 * 4]) = v;
    }
    __syncthreads();

    compute_tile(tile, w1p, w2p, w3p, w4p, op, tileX, tileY);
}

typedef CUresult (*PFN_tmapEncode)(
    CUtensorMap*, CUtensorMapDataType, cuuint32_t, void*,
    const cuuint64_t*, const cuuint64_t*, const cuuint32_t*, const cuuint32_t*,
    CUtensorMapInterleave, CUtensorMapSwizzle, CUtensorMapL2promotion,
    CUtensorMapFloatOOBfill);

extern "C" void kernel_launch(void* const* d_in, const int* in_sizes, int n_in,
                              void* d_out, int out_size)
{
    const float* s  = (const float*)d_in[0];
    const float* w1 = (const float*)d_in[1];
    const float* w2 = (const float*)d_in[2];
    const float* w3 = (const float*)d_in[3];
    const float* w4 = (const float*)d_in[4];
    float* out = (float*)d_out;

    const int n_img = in_sizes[0] / (IMG * IMG);       // 192
    dim3 grid(IMG / TX, IMG / TY, n_img);              // (4, 8, 192)

    // Resolve cuTensorMapEncodeTiled through the runtime (no -lcuda needed).
    static PFN_tmapEncode pfn = nullptr;
    static bool resolved = false;
    if (!resolved) {
        void* fp = nullptr;
        cudaDriverEntryPointQueryResult qr = cudaDriverEntryPointSymbolNotFound;
        if (cudaGetDriverEntryPointByVersion("cuTensorMapEncodeTiled", &fp, 12000,
                                             cudaEnableDefault, &qr) == cudaSuccess &&
            qr == cudaDriverEntryPointSuccess)
            pfn = (PFN_tmapEncode)fp;
        resolved = true;
    }

    CUtensorMap tmap;
    bool use_tma = false;
    if (pfn) {
        cuuint64_t dims[3]    = {IMG, IMG, (cuuint64_t)n_img};
        cuuint64_t strides[2] = {IMG * 4ull, (cuuint64_t)IMG * IMG * 4ull};
        cuuint32_t box[3]     = {SW, SH, 1};
        cuuint32_t estr[3]    = {1, 1, 1};
        use_tma = (pfn(&tmap, CU_TENSOR_MAP_DATA_TYPE_FLOAT32, 3, (void*)s,
                       dims, strides, box, estr,
                       CU_TENSOR_MAP_INTERLEAVE_NONE, CU_TENSOR_MAP_SWIZZLE_NONE,
                       CU_TENSOR_MAP_L2_PROMOTION_L2_128B,
                       CU_TENSOR_MAP_FLOAT_OOB_FILL_NONE) == CUDA_SUCCESS);
    }

    if (use_tma)
        mgdf_tma_kernel<<<grid, NTH>>>(tmap, w1, w2, w3, w4, out);
    else
        mgdf_ldg_kernel<<<grid, NTH>>>(s, w1, w2, w3, w4, out);
}

// round 10
// speedup vs baseline: 2.1733x; 1.0280x over previous
#include <cuda_runtime.h>
#include <cuda.h>

typedef unsigned long long ull;

// out = (w1+w2)*s + (w3-w2)*G3(s) + (w4-w3)*G5(s) - w4*G7(s)
// TMA tile fill (zero LSU/ALU load cost, OOB zero-fill = conv padding) +
// 4 cols/thread horizontal via 3x aligned LDS.128 (scalar FFMA-imm) +
// transposed-FIR f32x2 vertical ring. Tile 128x128, NTH=256, RPT=16, 3 CTAs/SM.

#define IMG 512
#define TX 128
#define TY 128
#define NTH 256
#define SW 136            // TX + 8 (left halo 4, right halo 4)
#define SH 134            // TY + 6
#define NF4 (SW / 4)
#define STEPS 22
#define TILE_BYTES (SH * SW * 4)   // 72896

#define K3_0 0.5220116f
#define K3_1 0.2389942f
#define K5_0 0.3695467f
#define K5_1 0.2444604f
#define K5_2 0.0707663f
#define K7_0 0.2880262f
#define K7_1 0.2231734f
#define K7_2 0.1038183f
#define K7_3 0.0289952f

__device__ __forceinline__ ull pk2(float lo, float hi) {
    ull r; asm("mov.b64 %0, {%1, %2};" : "=l"(r) : "f"(lo), "f"(hi)); return r;
}
__device__ __forceinline__ ull mul2(ull a, ull b) {
    ull r; asm("mul.rn.f32x2 %0, %1, %2;" : "=l"(r) : "l"(a), "l"(b)); return r;
}
__device__ __forceinline__ ull fma2(ull a, ull b, ull c) {
    ull r; asm("fma.rn.f32x2 %0, %1, %2, %3;" : "=l"(r) : "l"(a), "l"(b), "l"(c)); return r;
}
__device__ __forceinline__ unsigned smem_u32(const void* p) {
    unsigned r;
    asm("{ .reg .u64 t; cvta.to.shared.u64 t, %1; cvt.u32.u64 %0, t; }" : "=r"(r) : "l"(p));
    return r;
}

// ---- compute body: 4 cols/thread, 3x LDS.128 horizontal, f32x2 ring vertical ----
__device__ __forceinline__ void compute_tile(
    float (&tile)[SH][SW],
    const float* __restrict__ w1p, const float* __restrict__ w2p,
    const float* __restrict__ w3p, const float* __restrict__ w4p,
    float* __restrict__ op, int tileX, int tileY)
{
    const int tid = threadIdx.x;
    const float W1 = *w1p, W2 = *w2p, W3 = *w3p, W4 = *w4p;
    const float cA = W1 + W2, cB = W3 - W2, cC = W4 - W3, cD = -W4;
    const ull cAp = pk2(cA, cA);
    const ull a30 = pk2(cB * K3_0, cB * K3_0);
    const ull a31 = pk2(cB * K3_1, cB * K3_1);
    const ull a50 = pk2(cC * K5_0, cC * K5_0);
    const ull a51 = pk2(cC * K5_1, cC * K5_1);
    const ull a52 = pk2(cC * K5_2, cC * K5_2);
    const ull a70 = pk2(cD * K7_0, cD * K7_0);
    const ull a71 = pk2(cD * K7_1, cD * K7_1);
    const ull a72 = pk2(cD * K7_2, cD * K7_2);
    const ull a73 = pk2(cD * K7_3, cD * K7_3);

    const int xg = tid & 31;            // 32 col-groups of 4 cols
    const int rg = tid >> 5;            // 8 row-groups of 16 rows
    const int cb = 4 * xg;              // first float4; centers cb+4..cb+7
    const int rowBase = rg * 16;
    float* orow = op + (size_t)(tileY + rowBase) * IMG + tileX + 4 * xg;

    ull acc[7][2];

    #pragma unroll
    for (int k = 0; k < STEPS; k++) {
        const int sr = rowBase + k;

        // ---- horizontal: 3 aligned LDS.128 cover all 10 taps for 4 cols ----
        float4 A = *reinterpret_cast<const float4*>(&tile[sr][cb]);
        float4 Bv = *reinterpret_cast<const float4*>(&tile[sr][cb + 4]);
        float4 C = *reinterpret_cast<const float4*>(&tile[sr][cb + 8]);
        float x1 = A.y, x2 = A.z, x3 = A.w;
        float x4 = Bv.x, x5 = Bv.y, x6 = Bv.z, x7 = Bv.w;
        float x8 = C.x, x9 = C.y, x10 = C.z;

        float h3v[4], h5v[4], h7v[4];
        {
            float p1, p2, p3;
            p1 = x3 + x5;  p2 = x2 + x6;  p3 = x1 + x7;
            h3v[0] = K3_0 * x4 + K3_1 * p1;
            h5v[0] = K5_0 * x4 + K5_1 * p1 + K5_2 * p2;
            h7v[0] = K7_0 * x4 + K7_1 * p1 + K7_2 * p2 + K7_3 * p3;
            p1 = x4 + x6;  p2 = x3 + x7;  p3 = x2 + x8;
            h3v[1] = K3_0 * x5 + K3_1 * p1;
            h5v[1] = K5_0 * x5 + K5_1 * p1 + K5_2 * p2;
            h7v[1] = K7_0 * x5 + K7_1 * p1 + K7_2 * p2 + K7_3 * p3;
            p1 = x5 + x7;  p2 = x4 + x8;  p3 = x3 + x9;
            h3v[2] = K3_0 * x6 + K3_1 * p1;
            h5v[2] = K5_0 * x6 + K5_1 * p1 + K5_2 * p2;
            h7v[2] = K7_0 * x6 + K7_1 * p1 + K7_2 * p2 + K7_3 * p3;
            p1 = x6 + x8;  p2 = x5 + x9;  p3 = x4 + x10;
            h3v[3] = K3_0 * x7 + K3_1 * p1;
            h5v[3] = K5_0 * x7 + K5_1 * p1 + K5_2 * p2;
            h7v[3] = K7_0 * x7 + K7_1 * p1 + K7_2 * p2 + K7_3 * p3;
        }
        ull t3a = pk2(h3v[0], h3v[1]), t3b = pk2(h3v[2], h3v[3]);
        ull t5a = pk2(h5v[0], h5v[1]), t5b = pk2(h5v[2], h5v[3]);
        ull t7a = pk2(h7v[0], h7v[1]), t7b = pk2(h7v[2], h7v[3]);
        ull rwa = pk2(x4, x5),          rwb = pk2(x6, x7);

        // ---- transposed-FIR ring, 2 ull lanes ----
        if (k <= 15) {                                   // d=0 init
            acc[k % 7][0] = mul2(a73, t7a);
            acc[k % 7][1] = mul2(a73, t7b);
        }
        if (k >= 1 && k <= 16) {                         // d=1
            ull u = acc[(k - 1) % 7][0], v = acc[(k - 1) % 7][1];
            u = fma2(a72, t7a, u);  v = fma2(a72, t7b, v);
            u = fma2(a52, t5a, u);  v = fma2(a52, t5b, v);
            acc[(k - 1) % 7][0] = u; acc[(k - 1) % 7][1] = v;
        }
        if (k >= 2 && k <= 17) {                         // d=2
            ull u = acc[(k - 2) % 7][0], v = acc[(k - 2) % 7][1];
            u = fma2(a71, t7a, u);  v = fma2(a71, t7b, v);
            u = fma2(a51, t5a, u);  v = fma2(a51, t5b, v);
            u = fma2(a31, t3a, u);  v = fma2(a31, t3b, v);
            acc[(k - 2) % 7][0] = u; acc[(k - 2) % 7][1] = v;
        }
        if (k >= 3 && k <= 18) {                         // d=3 (center)
            ull u = acc[(k - 3) % 7][0], v = acc[(k - 3) % 7][1];
            u = fma2(a70, t7a, u);  v = fma2(a70, t7b, v);
            u = fma2(a50, t5a, u);  v = fma2(a50, t5b, v);
            u = fma2(a30, t3a, u);  v = fma2(a30, t3b, v);
            u = fma2(cAp, rwa, u);  v = fma2(cAp, rwb, v);
            acc[(k - 3) % 7][0] = u; acc[(k - 3) % 7][1] = v;
        }
        if (k >= 4 && k <= 19) {                         // d=4
            ull u = acc[(k - 4) % 7][0], v = acc[(k - 4) % 7][1];
            u = fma2(a71, t7a, u);  v = fma2(a71, t7b, v);
            u = fma2(a51, t5a, u);  v = fma2(a51, t5b, v);
            u = fma2(a31, t3a, u);  v = fma2(a31, t3b, v);
            acc[(k - 4) % 7][0] = u; acc[(k - 4) % 7][1] = v;
        }
        if (k >= 5 && k <= 20) {                         // d=5
            ull u = acc[(k - 5) % 7][0], v = acc[(k - 5) % 7][1];
            u = fma2(a72, t7a, u);  v = fma2(a72, t7b, v);
            u = fma2(a52, t5a, u);  v = fma2(a52, t5b, v);
            acc[(k - 5) % 7][0] = u; acc[(k - 5) % 7][1] = v;
        }
        if (k >= 6) {                                    // d=6: finish + STG.128
            ulonglong2 o;
            o.x = fma2(a73, t7a, acc[(k - 6) % 7][0]);
            o.y = fma2(a73, t7b, acc[(k - 6) % 7][1]);
            *reinterpret_cast<ulonglong2*>(orow + (size_t)(k - 6) * IMG) = o;
        }
    }
}

// ---- TMA kernel ----
__global__ void __launch_bounds__(NTH, 3)
mgdf_tma_kernel(const __grid_constant__ CUtensorMap tmap,
                const float* __restrict__ w1p, const float* __restrict__ w2p,
                const float* __restrict__ w3p, const float* __restrict__ w4p,
                float* __restrict__ out)
{
    __shared__ __align__(128) float tile[SH][SW];
    __shared__ __align__(8) ull mbar;

    const int tid = threadIdx.x;
    const int tileX = blockIdx.x * TX;
    const int tileY = blockIdx.y * TY;
    const int img = blockIdx.z;
    float* op = out + (size_t)img * (IMG * IMG);

    const unsigned mb = smem_u32(&mbar);
    if (tid == 0) {
        asm volatile("mbarrier.init.shared.b64 [%0], 1;" :: "r"(mb) : "memory");
    }
    __syncthreads();
    if (tid == 0) {
        asm volatile("mbarrier.arrive.expect_tx.shared.b64 _, [%0], %1;"
                     :: "r"(mb), "r"((unsigned)TILE_BYTES) : "memory");
        asm volatile(
            "cp.async.bulk.tensor.3d.shared::cta.global.tile.mbarrier::complete_tx::bytes "
            "[%0], [%1, {%2, %3, %4}], [%5];"
            :: "r"(smem_u32(&tile[0][0])), "l"(&tmap),
               "r"(tileX - 4), "r"(tileY - 3), "r"(img), "r"(mb)
            : "memory");
    }
    {
        unsigned done;
        asm volatile(
            "{\n\t.reg .pred p;\n\t"
            "mbarrier.try_wait.parity.acquire.cta.shared::cta.b64 p, [%1], 0;\n\t"
            "selp.b32 %0, 1, 0, p;\n\t}"
            : "=r"(done) : "r"(mb) : "memory");
        if (!done) {
            asm volatile(
                "{\n\t.reg .pred P1;\n\t"
                "W%=:\n\t"
                "mbarrier.try_wait.parity.acquire.cta.shared::cta.b64 P1, [%0], 0, 0x989680;\n\t"
                "@P1 bra.uni D%=;\n\t"
                "bra.uni W%=;\n\t"
                "D%=:\n\t}"
                :: "r"(mb) : "memory");
        }
    }

    compute_tile(tile, w1p, w2p, w3p, w4p, op, tileX, tileY);
}

// ---- fallback kernel (TMA encode unavailable) ----
__global__ void __launch_bounds__(NTH, 3)
mgdf_ldg_kernel(const float* __restrict__ s,
                const float* __restrict__ w1p, const float* __restrict__ w2p,
                const float* __restrict__ w3p, const float* __restrict__ w4p,
                float* __restrict__ out)
{
    __shared__ __align__(16) float tile[SH][SW];

    const int img = blockIdx.z;
    const size_t base = (size_t)img * (IMG * IMG);
    const float* sp = s + base;
    float* op = out + base;
    const int tileX = blockIdx.x * TX;
    const int tileY = blockIdx.y * TY;
    const int tid = threadIdx.x;

    #pragma unroll
    for (int idx = tid; idx < SH * NF4; idx += NTH) {
        int r = idx / NF4;
        int c4 = idx - r * NF4;
        int gy = tileY - 3 + r;
        int gx = tileX - 4 + c4 * 4;
        float4 v = make_float4(0.f, 0.f, 0.f, 0.f);
        if ((unsigned)gy < (unsigned)IMG && (unsigned)gx < (unsigned)IMG)
            v = *reinterpret_cast<const float4*>(sp + gy * IMG + gx);
        *reinterpret_cast<float4*>(&tile[r][c4 * 4]) = v;
    }
    __syncthreads();

    compute_tile(tile, w1p, w2p, w3p, w4p, op, tileX, tileY);
}

typedef CUresult (*PFN_tmapEncode)(
    CUtensorMap*, CUtensorMapDataType, cuuint32_t, void*,
    const cuuint64_t*, const cuuint64_t*, const cuuint32_t*, const cuuint32_t*,
    CUtensorMapInterleave, CUtensorMapSwizzle, CUtensorMapL2promotion,
    CUtensorMapFloatOOBfill);

extern "C" void kernel_launch(void* const* d_in, const int* in_sizes, int n_in,
                              void* d_out, int out_size)
{
    const float* s  = (const float*)d_in[0];
    const float* w1 = (const float*)d_in[1];
    const float* w2 = (const float*)d_in[2];
    const float* w3 = (const float*)d_in[3];
    const float* w4 = (const float*)d_in[4];
    float* out = (float*)d_out;

    const int n_img = in_sizes[0] / (IMG * IMG);       // 192
    dim3 grid(IMG / TX, IMG / TY, n_img);              // (4, 4, 192)

    static PFN_tmapEncode pfn = nullptr;
    static bool resolved = false;
    if (!resolved) {
        void* fp = nullptr;
        cudaDriverEntryPointQueryResult qr = cudaDriverEntryPointSymbolNotFound;
        if (cudaGetDriverEntryPointByVersion("cuTensorMapEncodeTiled", &fp, 12000,
                                             cudaEnableDefault, &qr) == cudaSuccess &&
            qr == cudaDriverEntryPointSuccess)
            pfn = (PFN_tmapEncode)fp;
        resolved = true;
    }

    CUtensorMap tmap;
    bool use_tma = false;
    if (pfn) {
        cuuint64_t dims[3]    = {IMG, IMG, (cuuint64_t)n_img};
        cuuint64_t strides[2] = {IMG * 4ull, (cuuint64_t)IMG * IMG * 4ull};
        cuuint32_t box[3]     = {SW, SH, 1};
        cuuint32_t estr[3]    = {1, 1, 1};
        use_tma = (pfn(&tmap, CU_TENSOR_MAP_DATA_TYPE_FLOAT32, 3, (void*)s,
                       dims, strides, box, estr,
                       CU_TENSOR_MAP_INTERLEAVE_NONE, CU_TENSOR_MAP_SWIZZLE_NONE,
                       CU_TENSOR_MAP_L2_PROMOTION_L2_128B,
                       CU_TENSOR_MAP_FLOAT_OOB_FILL_NONE) == CUDA_SUCCESS);
    }

    if (use_tma)
        mgdf_tma_kernel<<<grid, NTH>>>(tmap, w1, w2, w3, w4, out);
    else
        mgdf_ldg_kernel<<<grid, NTH>>>(s, w1, w2, w3, w4, out);
}